// round 8
// baseline (speedup 1.0000x reference)
#include <cuda_runtime.h>
#include <cstdint>
#include <cstddef>

#define TT_   512
#define BB_   256
#define HID   128
#define GATE  512
#define KSMH  36           // k-rows per group in smem
#define KRGH  28           // k-rows per group in registers (36+28 = 64 per group)

// Scratch (static device globals — allocation is forbidden)
__device__ float g_h1 [(size_t)TT_ * BB_ * 2 * HID];   // layer-0 output [t][b][256]
__device__ float g_g1f[(size_t)TT_ * BB_ * GATE];      // layer-1 fwd precomputed input gates
__device__ float g_h2f[BB_ * HID];                     // layer-1 fwd final h

// ---------------- packed f32x2 helpers ----------------
__device__ __forceinline__ unsigned long long pack2(float lo, float hi) {
    unsigned long long r;
    asm("mov.b64 %0, {%1, %2};" : "=l"(r) : "f"(lo), "f"(hi));
    return r;
}
__device__ __forceinline__ unsigned long long dup2(float v) {
    unsigned long long r;
    asm("mov.b64 %0, {%1, %1};" : "=l"(r) : "f"(v));
    return r;
}
__device__ __forceinline__ void unpack2(unsigned long long v, float& lo, float& hi) {
    asm("mov.b64 {%0, %1}, %2;" : "=f"(lo), "=f"(hi) : "l"(v));
}
__device__ __forceinline__ void ffma2(unsigned long long& d, unsigned long long a, unsigned long long b) {
    asm("fma.rn.f32x2 %0, %1, %2, %0;" : "+l"(d) : "l"(a), "l"(b));
}

// ---------------- activations (accurate ~1e-6) ----------------
__device__ __forceinline__ float sigm_f(float x) {
    return __fdividef(1.0f, 1.0f + __expf(-x));
}
__device__ __forceinline__ float tanh_f(float x) {
    float a = fabsf(x);
    float e = __expf(-2.0f * a);
    float r = __fdividef(1.0f - e, 1.0f + e);
    return copysignf(r, x);
}

// =====================================================================================
// Kernel 1: layer-0 bidirectional recurrence — GATE-PAIR + SPLIT-K (measured 4150 cfg)
// =====================================================================================
extern "C" __global__ void __launch_bounds__(512, 1)
lstm_l0(const float* __restrict__ x,
        const float* __restrict__ Wih_f, const float* __restrict__ Whh_f, const float* __restrict__ bv_f,
        const float* __restrict__ Wih_b, const float* __restrict__ Whh_b, const float* __restrict__ bv_b)
{
    extern __shared__ float sm0[];
    float* Wsm = sm0;                      // [2][KSMH][512]
    float* hsm = sm0 + 2 * KSMH * 512;     // [2][128][8]   (h,h) duplicated, 4 rows
    float* gsm = hsm + 2048;               // [2][4][512]   partial gates per group
    float* xsm = gsm + 4096;               // [2][12]

    const int tid = threadIdx.x;
    const int g   = tid >> 8;              // k-group
    const int t   = tid & 255;
    const int j0  = 2 * t;                 // owned gate columns
    const int dir = blockIdx.y;
    const int b0  = blockIdx.x * 4;
    const float* __restrict__ Wih = dir ? Wih_b : Wih_f;
    const float* __restrict__ Whh = dir ? Whh_b : Whh_f;
    const float* __restrict__ bv  = dir ? bv_b  : bv_f;

    for (int idx = tid; idx < 2 * KSMH * 512; idx += 512) {
        int gg  = idx / (KSMH * 512);
        int rem = idx - gg * (KSMH * 512);
        int kk  = rem >> 9, col = rem & 511;
        Wsm[idx] = Whh[col * HID + gg * 64 + kk];
    }
    unsigned long long wreg[KRGH];
#pragma unroll
    for (int r = 0; r < KRGH; r++) {
        int k = g * 64 + KSMH + r;
        wreg[r] = pack2(Whh[j0 * HID + k], Whh[(j0 + 1) * HID + k]);
    }

    float wA0 = Wih[j0 * 3], wA1 = Wih[j0 * 3 + 1], wA2 = Wih[j0 * 3 + 2];
    float wB0 = Wih[(j0 + 1) * 3], wB1 = Wih[(j0 + 1) * 3 + 1], wB2 = Wih[(j0 + 1) * 3 + 2];
    float bA = bv[j0], bB = bv[j0 + 1];

#pragma unroll
    for (int i = 0; i < 4; i++) hsm[tid + 512 * i] = 0.0f;
    if (tid < 12) {
        int r = tid / 3, i = tid % 3;
        int t0 = dir ? (TT_ - 1) : 0;
        xsm[tid] = x[((size_t)(b0 + r) * TT_ + t0) * 3 + i];
    }
    const int u  = tid & 127;
    const int bb = tid >> 7;
    float c = 0.0f;
    const float* wp = Wsm + g * (KSMH * 512) + j0;
    __syncthreads();

    for (int s = 0; s < TT_; s++) {
        const int tcur = dir ? (TT_ - 1 - s) : s;
        const int pb = s & 1;

        unsigned long long acc[4];
        if (g == 0) {
            const float* xp = xsm + pb * 12;
#pragma unroll
            for (int b = 0; b < 4; b++) {
                float xx0 = xp[b * 3], xx1 = xp[b * 3 + 1], xx2 = xp[b * 3 + 2];
                float aA = fmaf(wA2, xx2, fmaf(wA1, xx1, fmaf(wA0, xx0, bA)));
                float aB = fmaf(wB2, xx2, fmaf(wB1, xx1, fmaf(wB0, xx0, bB)));
                acc[b] = pack2(aA, aB);
            }
        } else {
#pragma unroll
            for (int b = 0; b < 4; b++) acc[b] = 0ULL;
        }

        const float* hb = hsm + pb * 1024 + g * (64 * 8);
#pragma unroll 9
        for (int kk = 0; kk < KSMH; kk++) {
            unsigned long long w2 = *reinterpret_cast<const unsigned long long*>(wp + kk * 512);
            ulonglong2 H01 = *reinterpret_cast<const ulonglong2*>(hb + kk * 8);
            ulonglong2 H23 = *reinterpret_cast<const ulonglong2*>(hb + kk * 8 + 4);
            ffma2(acc[0], w2, H01.x);
            ffma2(acc[1], w2, H01.y);
            ffma2(acc[2], w2, H23.x);
            ffma2(acc[3], w2, H23.y);
        }
#pragma unroll
        for (int r = 0; r < KRGH; r++) {
            ulonglong2 H01 = *reinterpret_cast<const ulonglong2*>(hb + (KSMH + r) * 8);
            ulonglong2 H23 = *reinterpret_cast<const ulonglong2*>(hb + (KSMH + r) * 8 + 4);
            ffma2(acc[0], wreg[r], H01.x);
            ffma2(acc[1], wreg[r], H01.y);
            ffma2(acc[2], wreg[r], H23.x);
            ffma2(acc[3], wreg[r], H23.y);
        }
#pragma unroll
        for (int b = 0; b < 4; b++)
            *reinterpret_cast<unsigned long long*>(gsm + g * 2048 + b * 512 + j0) = acc[b];
        __syncthreads();

        {
            const float* g0 = gsm + bb * 512;
            const float* g1 = gsm + 2048 + bb * 512;
            float gi = g0[u]       + g1[u];
            float gf = g0[u + 128] + g1[u + 128];
            float gg = g0[u + 256] + g1[u + 256];
            float go = g0[u + 384] + g1[u + 384];
            c = sigm_f(gf) * c + sigm_f(gi) * tanh_f(gg);
            float h = sigm_f(go) * tanh_f(c);

            *reinterpret_cast<float2*>(hsm + (pb ^ 1) * 1024 + u * 8 + bb * 2) =
                make_float2(h, h);
            g_h1[((size_t)tcur * BB_ + b0 + bb) * (2 * HID) + dir * HID + u] = h;
        }
        if (s + 1 < TT_ && tid < 12) {
            int r = tid / 3, i = tid % 3;
            int tn = dir ? (TT_ - 2 - s) : (s + 1);
            xsm[(pb ^ 1) * 12 + tid] = x[((size_t)(b0 + r) * TT_ + tn) * 3 + i];
        }
        __syncthreads();
    }
}

// =====================================================================================
// Kernel 2: layer-1 forward input projection GEMM (measured 4150 cfg)
// =====================================================================================
#define APITCH 68
#define WPITCH 129
extern "C" __global__ void __launch_bounds__(512, 1)
gemm_l1in(const float* __restrict__ W, const float* __restrict__ bias)
{
    extern __shared__ float smg[];
    float* Asm = smg;                    // [256][APITCH]
    float* Wsm = smg + 256 * APITCH;     // [256][WPITCH]

    const int tid  = threadIdx.x;
    const int jblk = blockIdx.x & 3;
    const int tg   = blockIdx.x >> 2;

    for (int idx = tid; idx < 128 * 256; idx += 512) {
        int k = idx & 255, jj = idx >> 8;
        Wsm[k * WPITCH + jj] = W[((jblk << 7) + jj) * 256 + k];
    }

    const int j  = tid & 127;
    const int rg = tid >> 7;
    const float bj = bias[(jblk << 7) + j];
    const unsigned long long bpack = pack2(bj, bj);

    for (int tile = tg; tile < 2048; tile += 37) {
        const size_t r0 = (size_t)tile * 64;
        __syncthreads();
        for (int idx = tid; idx < 64 * 256; idx += 512) {
            int k = idx & 255, row = idx >> 8;
            Asm[k * APITCH + row] = g_h1[(r0 + row) * 256 + k];
        }
        __syncthreads();

        unsigned long long acc[8];
#pragma unroll
        for (int p = 0; p < 8; p++) acc[p] = bpack;

#pragma unroll 4
        for (int k = 0; k < 256; k++) {
            unsigned long long w2 = dup2(Wsm[k * WPITCH + j]);
            const ulonglong2* ap =
                reinterpret_cast<const ulonglong2*>(Asm + k * APITCH + rg * 16);
#pragma unroll
            for (int q = 0; q < 4; q++) {
                ulonglong2 av = ap[q];
                ffma2(acc[2 * q],     w2, av.x);
                ffma2(acc[2 * q + 1], w2, av.y);
            }
        }
#pragma unroll
        for (int p = 0; p < 8; p++) {
            float v0, v1; unpack2(acc[p], v0, v1);
            size_t r = r0 + rg * 16 + 2 * p;
            g_g1f[r * GATE + (jblk << 7) + j]       = v0;
            g_g1f[(r + 1) * GATE + (jblk << 7) + j] = v1;
        }
    }
}

// =====================================================================================
// Kernel 3: layer-1 forward recurrence — GATE-PAIR + SPLIT-K (measured 4150 cfg)
// =====================================================================================
extern "C" __global__ void __launch_bounds__(512, 1)
lstm_l1(const float* __restrict__ Whh)
{
    extern __shared__ float sm1[];
    float* Wsm = sm1;                     // [2][KSMH][512]
    float* hsm = sm1 + 2 * KSMH * 512;    // [2][128][4]  (h0,h0,h1,h1)
    float* gsm = hsm + 1024;              // [2][2][512]  partial gates per group

    const int tid = threadIdx.x;
    const int g   = tid >> 8;
    const int t   = tid & 255;
    const int j0  = 2 * t;
    const int b0  = blockIdx.x * 2;

    for (int idx = tid; idx < 2 * KSMH * 512; idx += 512) {
        int gg  = idx / (KSMH * 512);
        int rem = idx - gg * (KSMH * 512);
        int kk  = rem >> 9, col = rem & 511;
        Wsm[idx] = Whh[col * HID + gg * 64 + kk];
    }
    unsigned long long wreg[KRGH];
#pragma unroll
    for (int r = 0; r < KRGH; r++) {
        int k = g * 64 + KSMH + r;
        wreg[r] = pack2(Whh[j0 * HID + k], Whh[(j0 + 1) * HID + k]);
    }

#pragma unroll
    for (int i = 0; i < 2; i++) hsm[tid + 512 * i] = 0.0f;

    unsigned long long p0 = 0ULL, p1 = 0ULL;
    if (g == 0) {
        p0 = *reinterpret_cast<const unsigned long long*>(g_g1f + (size_t)(b0 + 0) * GATE + j0);
        p1 = *reinterpret_cast<const unsigned long long*>(g_g1f + (size_t)(b0 + 1) * GATE + j0);
    }

    const int u = tid & 127, bsel = (tid >> 7) & 1;
    const bool docell = tid < 256;
    float c = 0.0f;
    const float* wp = Wsm + g * (KSMH * 512) + j0;
    __syncthreads();

    for (int s = 0; s < TT_; s++) {
        const int pb = s & 1;
        unsigned long long acc0 = p0, acc1 = p1;

        if (g == 0 && s + 1 < TT_) {
            size_t rn = (size_t)(s + 1) * BB_ + b0;
            p0 = *reinterpret_cast<const unsigned long long*>(g_g1f + rn * GATE + j0);
            p1 = *reinterpret_cast<const unsigned long long*>(g_g1f + (rn + 1) * GATE + j0);
        }

        const float* hb = hsm + pb * 512 + g * (64 * 4);
#pragma unroll 9
        for (int kk = 0; kk < KSMH; kk++) {
            unsigned long long w2 = *reinterpret_cast<const unsigned long long*>(wp + kk * 512);
            ulonglong2 H = *reinterpret_cast<const ulonglong2*>(hb + kk * 4);
            ffma2(acc0, w2, H.x);
            ffma2(acc1, w2, H.y);
        }
#pragma unroll
        for (int r = 0; r < KRGH; r++) {
            ulonglong2 H = *reinterpret_cast<const ulonglong2*>(hb + (KSMH + r) * 4);
            ffma2(acc0, wreg[r], H.x);
            ffma2(acc1, wreg[r], H.y);
        }
        *reinterpret_cast<unsigned long long*>(gsm + g * 1024 + 0 * 512 + j0) = acc0;
        *reinterpret_cast<unsigned long long*>(gsm + g * 1024 + 1 * 512 + j0) = acc1;
        __syncthreads();

        if (docell) {
            const float* ga = gsm + bsel * 512;
            const float* gb2 = gsm + 1024 + bsel * 512;
            float gi = ga[u]       + gb2[u];
            float gf = ga[u + 128] + gb2[u + 128];
            float gg = ga[u + 256] + gb2[u + 256];
            float go = ga[u + 384] + gb2[u + 384];
            c = sigm_f(gf) * c + sigm_f(gi) * tanh_f(gg);
            float h = sigm_f(go) * tanh_f(c);
            *reinterpret_cast<float2*>(hsm + (pb ^ 1) * 512 + u * 4 + bsel * 2) =
                make_float2(h, h);
            if (s == TT_ - 1) g_h2f[(b0 + bsel) * HID + u] = h;
        }
        __syncthreads();
    }
}

// =====================================================================================
// Kernel 4: layer-1 backward single step + FC (measured 4150 cfg)
// =====================================================================================
extern "C" __global__ void __launch_bounds__(512, 1)
final_k(const float* __restrict__ Wihb, const float* __restrict__ bvb,
        const float* __restrict__ Wfc,  const float* __restrict__ bfc,
        float* __restrict__ out)
{
    __shared__ float h1s[4 * 256];
    __shared__ float hfs[4 * 128];
    __shared__ float gates[4 * 512];
    __shared__ float hbs[4 * 128];

    const int tid = threadIdx.x;
    const int b0  = blockIdx.x * 4;

    for (int idx = tid; idx < 4 * 256; idx += 512) {
        int r = idx >> 8, k = idx & 255;
        h1s[idx] = g_h1[((size_t)(TT_ - 1) * BB_ + b0 + r) * 256 + k];
    }
    if (tid < 4 * 128)
        hfs[tid] = g_h2f[b0 * HID + tid];
    __syncthreads();

    float acc[4];
    const float bj = bvb[tid];
#pragma unroll
    for (int r = 0; r < 4; r++) acc[r] = bj;
    const float* wr = Wihb + (size_t)tid * 256;
#pragma unroll 4
    for (int k = 0; k < 256; k++) {
        float w = wr[k];
#pragma unroll
        for (int r = 0; r < 4; r++) acc[r] = fmaf(h1s[r * 256 + k], w, acc[r]);
    }
#pragma unroll
    for (int r = 0; r < 4; r++) gates[r * 512 + tid] = acc[r];
    __syncthreads();

    {
        int r = tid >> 7, u = tid & 127;
        float gi = gates[r * 512 + u];
        float gg = gates[r * 512 + u + 256];
        float go = gates[r * 512 + u + 384];
        float c  = sigm_f(gi) * tanh_f(gg);          // f-gate x c0 = 0
        hbs[r * 128 + u] = sigm_f(go) * tanh_f(c);
    }
    __syncthreads();

    if (tid < 24) {
        int r = tid / 6, o = tid % 6;
        const float* wf = Wfc + o * 256;
        float s0 = bfc[o], s1 = 0.0f;
#pragma unroll 4
        for (int jj = 0; jj < 128; jj++) {
            s0 = fmaf(hfs[r * 128 + jj], wf[jj],       s0);
            s1 = fmaf(hbs[r * 128 + jj], wf[128 + jj], s1);
        }
        out[(b0 + r) * 6 + o] = s0 + s1;
    }
}

// =====================================================================================
// DIAGNOSTIC ROUND: lstm_l0 and lstm_l1 are launched TWICE each (idempotent —
// identical inputs produce identical outputs, so the duplicate is deterministic and
// graph-safe). dur_us_new - dur_us_R7 = t_l0 + t_l1, which decomposes the total:
//   t_gemm = 4150 - 82(final) - (t_l0 + t_l1).
// =====================================================================================
extern "C" void kernel_launch(void* const* d_in, const int* in_sizes, int n_in,
                              void* d_out, int out_size)
{
    (void)in_sizes; (void)n_in; (void)out_size;
    const float* x     = (const float*)d_in[0];
    const float* Wih0f = (const float*)d_in[1];
    const float* Whh0f = (const float*)d_in[2];
    const float* b0f   = (const float*)d_in[3];
    const float* Wih0b = (const float*)d_in[4];
    const float* Whh0b = (const float*)d_in[5];
    const float* b0b   = (const float*)d_in[6];
    const float* Wih1f = (const float*)d_in[7];
    const float* Whh1f = (const float*)d_in[8];
    const float* b1f   = (const float*)d_in[9];
    const float* Wih1b = (const float*)d_in[10];
    const float* Whh1b = (const float*)d_in[11];
    const float* b1b   = (const float*)d_in[12];
    const float* Wfc   = (const float*)d_in[13];
    const float* bfc   = (const float*)d_in[14];
    float* out = (float*)d_out;

    const int SM_L0 = (2 * KSMH * 512 + 2048 + 4096 + 24) * 4;
    const int SM_G  = (256 * APITCH + 256 * WPITCH) * 4;
    const int SM_L1 = (2 * KSMH * 512 + 1024 + 2048) * 4;

    cudaFuncSetAttribute(lstm_l0,   cudaFuncAttributeMaxDynamicSharedMemorySize, SM_L0);
    cudaFuncSetAttribute(gemm_l1in, cudaFuncAttributeMaxDynamicSharedMemorySize, SM_G);
    cudaFuncSetAttribute(lstm_l1,   cudaFuncAttributeMaxDynamicSharedMemorySize, SM_L1);

    // duplicated launches (diagnostic timing decomposition)
    lstm_l0<<<dim3(64, 2), 512, SM_L0>>>(x, Wih0f, Whh0f, b0f, Wih0b, Whh0b, b0b);
    lstm_l0<<<dim3(64, 2), 512, SM_L0>>>(x, Wih0f, Whh0f, b0f, Wih0b, Whh0b, b0b);
    gemm_l1in<<<148, 512, SM_G>>>(Wih1f, b1f);
    lstm_l1<<<128, 512, SM_L1>>>(Whh1f);
    lstm_l1<<<128, 512, SM_L1>>>(Whh1f);
    final_k<<<64, 512>>>(Wih1b, b1b, Wfc, bfc, out);
}

// round 9
// speedup vs baseline: 1.0022x; 1.0022x over previous
#include <cuda_runtime.h>
#include <cstdint>
#include <cstddef>

#define TT_   512
#define BB_   256
#define HID   128
#define GATE  512
#define KSMH  36           // k-rows per group in smem
#define KRGH  28           // k-rows per group in registers (36+28 = 64 per group)

// Scratch (static device globals — allocation is forbidden)
__device__ float g_h1 [(size_t)TT_ * BB_ * 2 * HID];   // layer-0 output [t][b][256]
__device__ float g_g1f[(size_t)TT_ * BB_ * GATE];      // layer-1 fwd precomputed input gates
__device__ float g_h2f[BB_ * HID];                     // layer-1 fwd final h

// ---------------- packed f32x2 helpers ----------------
__device__ __forceinline__ unsigned long long pack2(float lo, float hi) {
    unsigned long long r;
    asm("mov.b64 %0, {%1, %2};" : "=l"(r) : "f"(lo), "f"(hi));
    return r;
}
__device__ __forceinline__ unsigned long long dup2(float v) {
    unsigned long long r;
    asm("mov.b64 %0, {%1, %1};" : "=l"(r) : "f"(v));
    return r;
}
__device__ __forceinline__ void unpack2(unsigned long long v, float& lo, float& hi) {
    asm("mov.b64 {%0, %1}, %2;" : "=f"(lo), "=f"(hi) : "l"(v));
}
__device__ __forceinline__ void ffma2(unsigned long long& d, unsigned long long a, unsigned long long b) {
    asm("fma.rn.f32x2 %0, %1, %2, %0;" : "+l"(d) : "l"(a), "l"(b));
}

// ---------------- activations (accurate ~1e-6) ----------------
__device__ __forceinline__ float sigm_f(float x) {
    return __fdividef(1.0f, 1.0f + __expf(-x));
}
__device__ __forceinline__ float tanh_f(float x) {
    float a = fabsf(x);
    float e = __expf(-2.0f * a);
    float r = __fdividef(1.0f - e, 1.0f + e);
    return copysignf(r, x);
}

// =====================================================================================
// Kernel 1: layer-0 bidirectional recurrence — GATE-PAIR + SPLIT-K (measured 4150 cfg)
// =====================================================================================
extern "C" __global__ void __launch_bounds__(512, 1)
lstm_l0(const float* __restrict__ x,
        const float* __restrict__ Wih_f, const float* __restrict__ Whh_f, const float* __restrict__ bv_f,
        const float* __restrict__ Wih_b, const float* __restrict__ Whh_b, const float* __restrict__ bv_b)
{
    extern __shared__ float sm0[];
    float* Wsm = sm0;                      // [2][KSMH][512]
    float* hsm = sm0 + 2 * KSMH * 512;     // [2][128][8]   (h,h) duplicated, 4 rows
    float* gsm = hsm + 2048;               // [2][4][512]   partial gates per group
    float* xsm = gsm + 4096;               // [2][12]

    const int tid = threadIdx.x;
    const int g   = tid >> 8;              // k-group
    const int t   = tid & 255;
    const int j0  = 2 * t;                 // owned gate columns
    const int dir = blockIdx.y;
    const int b0  = blockIdx.x * 4;
    const float* __restrict__ Wih = dir ? Wih_b : Wih_f;
    const float* __restrict__ Whh = dir ? Whh_b : Whh_f;
    const float* __restrict__ bv  = dir ? bv_b  : bv_f;

    for (int idx = tid; idx < 2 * KSMH * 512; idx += 512) {
        int gg  = idx / (KSMH * 512);
        int rem = idx - gg * (KSMH * 512);
        int kk  = rem >> 9, col = rem & 511;
        Wsm[idx] = Whh[col * HID + gg * 64 + kk];
    }
    unsigned long long wreg[KRGH];
#pragma unroll
    for (int r = 0; r < KRGH; r++) {
        int k = g * 64 + KSMH + r;
        wreg[r] = pack2(Whh[j0 * HID + k], Whh[(j0 + 1) * HID + k]);
    }

    float wA0 = Wih[j0 * 3], wA1 = Wih[j0 * 3 + 1], wA2 = Wih[j0 * 3 + 2];
    float wB0 = Wih[(j0 + 1) * 3], wB1 = Wih[(j0 + 1) * 3 + 1], wB2 = Wih[(j0 + 1) * 3 + 2];
    float bA = bv[j0], bB = bv[j0 + 1];

#pragma unroll
    for (int i = 0; i < 4; i++) hsm[tid + 512 * i] = 0.0f;
    if (tid < 12) {
        int r = tid / 3, i = tid % 3;
        int t0 = dir ? (TT_ - 1) : 0;
        xsm[tid] = x[((size_t)(b0 + r) * TT_ + t0) * 3 + i];
    }
    const int u  = tid & 127;
    const int bb = tid >> 7;
    float c = 0.0f;
    const float* wp = Wsm + g * (KSMH * 512) + j0;
    __syncthreads();

    for (int s = 0; s < TT_; s++) {
        const int tcur = dir ? (TT_ - 1 - s) : s;
        const int pb = s & 1;

        unsigned long long acc[4];
        if (g == 0) {
            const float* xp = xsm + pb * 12;
#pragma unroll
            for (int b = 0; b < 4; b++) {
                float xx0 = xp[b * 3], xx1 = xp[b * 3 + 1], xx2 = xp[b * 3 + 2];
                float aA = fmaf(wA2, xx2, fmaf(wA1, xx1, fmaf(wA0, xx0, bA)));
                float aB = fmaf(wB2, xx2, fmaf(wB1, xx1, fmaf(wB0, xx0, bB)));
                acc[b] = pack2(aA, aB);
            }
        } else {
#pragma unroll
            for (int b = 0; b < 4; b++) acc[b] = 0ULL;
        }

        const float* hb = hsm + pb * 1024 + g * (64 * 8);
#pragma unroll 9
        for (int kk = 0; kk < KSMH; kk++) {
            unsigned long long w2 = *reinterpret_cast<const unsigned long long*>(wp + kk * 512);
            ulonglong2 H01 = *reinterpret_cast<const ulonglong2*>(hb + kk * 8);
            ulonglong2 H23 = *reinterpret_cast<const ulonglong2*>(hb + kk * 8 + 4);
            ffma2(acc[0], w2, H01.x);
            ffma2(acc[1], w2, H01.y);
            ffma2(acc[2], w2, H23.x);
            ffma2(acc[3], w2, H23.y);
        }
#pragma unroll
        for (int r = 0; r < KRGH; r++) {
            ulonglong2 H01 = *reinterpret_cast<const ulonglong2*>(hb + (KSMH + r) * 8);
            ulonglong2 H23 = *reinterpret_cast<const ulonglong2*>(hb + (KSMH + r) * 8 + 4);
            ffma2(acc[0], wreg[r], H01.x);
            ffma2(acc[1], wreg[r], H01.y);
            ffma2(acc[2], wreg[r], H23.x);
            ffma2(acc[3], wreg[r], H23.y);
        }
#pragma unroll
        for (int b = 0; b < 4; b++)
            *reinterpret_cast<unsigned long long*>(gsm + g * 2048 + b * 512 + j0) = acc[b];
        __syncthreads();

        {
            const float* g0 = gsm + bb * 512;
            const float* g1 = gsm + 2048 + bb * 512;
            float gi = g0[u]       + g1[u];
            float gf = g0[u + 128] + g1[u + 128];
            float gg = g0[u + 256] + g1[u + 256];
            float go = g0[u + 384] + g1[u + 384];
            c = sigm_f(gf) * c + sigm_f(gi) * tanh_f(gg);
            float h = sigm_f(go) * tanh_f(c);

            *reinterpret_cast<float2*>(hsm + (pb ^ 1) * 1024 + u * 8 + bb * 2) =
                make_float2(h, h);
            g_h1[((size_t)tcur * BB_ + b0 + bb) * (2 * HID) + dir * HID + u] = h;
        }
        if (s + 1 < TT_ && tid < 12) {
            int r = tid / 3, i = tid % 3;
            int tn = dir ? (TT_ - 2 - s) : (s + 1);
            xsm[(pb ^ 1) * 12 + tid] = x[((size_t)(b0 + r) * TT_ + tn) * 3 + i];
        }
        __syncthreads();
    }
}

// =====================================================================================
// Kernel 2: layer-1 forward input projection GEMM (measured 4150 cfg)
// =====================================================================================
#define APITCH 68
#define WPITCH 129
extern "C" __global__ void __launch_bounds__(512, 1)
gemm_l1in(const float* __restrict__ W, const float* __restrict__ bias)
{
    extern __shared__ float smg[];
    float* Asm = smg;                    // [256][APITCH]
    float* Wsm = smg + 256 * APITCH;     // [256][WPITCH]

    const int tid  = threadIdx.x;
    const int jblk = blockIdx.x & 3;
    const int tg   = blockIdx.x >> 2;

    for (int idx = tid; idx < 128 * 256; idx += 512) {
        int k = idx & 255, jj = idx >> 8;
        Wsm[k * WPITCH + jj] = W[((jblk << 7) + jj) * 256 + k];
    }

    const int j  = tid & 127;
    const int rg = tid >> 7;
    const float bj = bias[(jblk << 7) + j];
    const unsigned long long bpack = pack2(bj, bj);

    for (int tile = tg; tile < 2048; tile += 37) {
        const size_t r0 = (size_t)tile * 64;
        __syncthreads();
        for (int idx = tid; idx < 64 * 256; idx += 512) {
            int k = idx & 255, row = idx >> 8;
            Asm[k * APITCH + row] = g_h1[(r0 + row) * 256 + k];
        }
        __syncthreads();

        unsigned long long acc[8];
#pragma unroll
        for (int p = 0; p < 8; p++) acc[p] = bpack;

#pragma unroll 4
        for (int k = 0; k < 256; k++) {
            unsigned long long w2 = dup2(Wsm[k * WPITCH + j]);
            const ulonglong2* ap =
                reinterpret_cast<const ulonglong2*>(Asm + k * APITCH + rg * 16);
#pragma unroll
            for (int q = 0; q < 4; q++) {
                ulonglong2 av = ap[q];
                ffma2(acc[2 * q],     w2, av.x);
                ffma2(acc[2 * q + 1], w2, av.y);
            }
        }
#pragma unroll
        for (int p = 0; p < 8; p++) {
            float v0, v1; unpack2(acc[p], v0, v1);
            size_t r = r0 + rg * 16 + 2 * p;
            g_g1f[r * GATE + (jblk << 7) + j]       = v0;
            g_g1f[(r + 1) * GATE + (jblk << 7) + j] = v1;
        }
    }
}

// =====================================================================================
// Kernel 3: layer-1 forward recurrence — GATE-PAIR + SPLIT-K (measured 4150 cfg)
// =====================================================================================
extern "C" __global__ void __launch_bounds__(512, 1)
lstm_l1(const float* __restrict__ Whh)
{
    extern __shared__ float sm1[];
    float* Wsm = sm1;                     // [2][KSMH][512]
    float* hsm = sm1 + 2 * KSMH * 512;    // [2][128][4]  (h0,h0,h1,h1)
    float* gsm = hsm + 1024;              // [2][2][512]  partial gates per group

    const int tid = threadIdx.x;
    const int g   = tid >> 8;
    const int t   = tid & 255;
    const int j0  = 2 * t;
    const int b0  = blockIdx.x * 2;

    for (int idx = tid; idx < 2 * KSMH * 512; idx += 512) {
        int gg  = idx / (KSMH * 512);
        int rem = idx - gg * (KSMH * 512);
        int kk  = rem >> 9, col = rem & 511;
        Wsm[idx] = Whh[col * HID + gg * 64 + kk];
    }
    unsigned long long wreg[KRGH];
#pragma unroll
    for (int r = 0; r < KRGH; r++) {
        int k = g * 64 + KSMH + r;
        wreg[r] = pack2(Whh[j0 * HID + k], Whh[(j0 + 1) * HID + k]);
    }

#pragma unroll
    for (int i = 0; i < 2; i++) hsm[tid + 512 * i] = 0.0f;

    unsigned long long p0 = 0ULL, p1 = 0ULL;
    if (g == 0) {
        p0 = *reinterpret_cast<const unsigned long long*>(g_g1f + (size_t)(b0 + 0) * GATE + j0);
        p1 = *reinterpret_cast<const unsigned long long*>(g_g1f + (size_t)(b0 + 1) * GATE + j0);
    }

    const int u = tid & 127, bsel = (tid >> 7) & 1;
    const bool docell = tid < 256;
    float c = 0.0f;
    const float* wp = Wsm + g * (KSMH * 512) + j0;
    __syncthreads();

    for (int s = 0; s < TT_; s++) {
        const int pb = s & 1;
        unsigned long long acc0 = p0, acc1 = p1;

        if (g == 0 && s + 1 < TT_) {
            size_t rn = (size_t)(s + 1) * BB_ + b0;
            p0 = *reinterpret_cast<const unsigned long long*>(g_g1f + rn * GATE + j0);
            p1 = *reinterpret_cast<const unsigned long long*>(g_g1f + (rn + 1) * GATE + j0);
        }

        const float* hb = hsm + pb * 512 + g * (64 * 4);
#pragma unroll 9
        for (int kk = 0; kk < KSMH; kk++) {
            unsigned long long w2 = *reinterpret_cast<const unsigned long long*>(wp + kk * 512);
            ulonglong2 H = *reinterpret_cast<const ulonglong2*>(hb + kk * 4);
            ffma2(acc0, w2, H.x);
            ffma2(acc1, w2, H.y);
        }
#pragma unroll
        for (int r = 0; r < KRGH; r++) {
            ulonglong2 H = *reinterpret_cast<const ulonglong2*>(hb + (KSMH + r) * 4);
            ffma2(acc0, wreg[r], H.x);
            ffma2(acc1, wreg[r], H.y);
        }
        *reinterpret_cast<unsigned long long*>(gsm + g * 1024 + 0 * 512 + j0) = acc0;
        *reinterpret_cast<unsigned long long*>(gsm + g * 1024 + 1 * 512 + j0) = acc1;
        __syncthreads();

        if (docell) {
            const float* ga = gsm + bsel * 512;
            const float* gb2 = gsm + 1024 + bsel * 512;
            float gi = ga[u]       + gb2[u];
            float gf = ga[u + 128] + gb2[u + 128];
            float gg = ga[u + 256] + gb2[u + 256];
            float go = ga[u + 384] + gb2[u + 384];
            c = sigm_f(gf) * c + sigm_f(gi) * tanh_f(gg);
            float h = sigm_f(go) * tanh_f(c);
            *reinterpret_cast<float2*>(hsm + (pb ^ 1) * 512 + u * 4 + bsel * 2) =
                make_float2(h, h);
            if (s == TT_ - 1) g_h2f[(b0 + bsel) * HID + u] = h;
        }
        __syncthreads();
    }
}

// =====================================================================================
// Kernel 4: layer-1 backward single step + FC (measured 4150 cfg)
// =====================================================================================
extern "C" __global__ void __launch_bounds__(512, 1)
final_k(const float* __restrict__ Wihb, const float* __restrict__ bvb,
        const float* __restrict__ Wfc,  const float* __restrict__ bfc,
        float* __restrict__ out)
{
    __shared__ float h1s[4 * 256];
    __shared__ float hfs[4 * 128];
    __shared__ float gates[4 * 512];
    __shared__ float hbs[4 * 128];

    const int tid = threadIdx.x;
    const int b0  = blockIdx.x * 4;

    for (int idx = tid; idx < 4 * 256; idx += 512) {
        int r = idx >> 8, k = idx & 255;
        h1s[idx] = g_h1[((size_t)(TT_ - 1) * BB_ + b0 + r) * 256 + k];
    }
    if (tid < 4 * 128)
        hfs[tid] = g_h2f[b0 * HID + tid];
    __syncthreads();

    float acc[4];
    const float bj = bvb[tid];
#pragma unroll
    for (int r = 0; r < 4; r++) acc[r] = bj;
    const float* wr = Wihb + (size_t)tid * 256;
#pragma unroll 4
    for (int k = 0; k < 256; k++) {
        float w = wr[k];
#pragma unroll
        for (int r = 0; r < 4; r++) acc[r] = fmaf(h1s[r * 256 + k], w, acc[r]);
    }
#pragma unroll
    for (int r = 0; r < 4; r++) gates[r * 512 + tid] = acc[r];
    __syncthreads();

    {
        int r = tid >> 7, u = tid & 127;
        float gi = gates[r * 512 + u];
        float gg = gates[r * 512 + u + 256];
        float go = gates[r * 512 + u + 384];
        float c  = sigm_f(gi) * tanh_f(gg);          // f-gate x c0 = 0
        hbs[r * 128 + u] = sigm_f(go) * tanh_f(c);
    }
    __syncthreads();

    if (tid < 24) {
        int r = tid / 6, o = tid % 6;
        const float* wf = Wfc + o * 256;
        float s0 = bfc[o], s1 = 0.0f;
#pragma unroll 4
        for (int jj = 0; jj < 128; jj++) {
            s0 = fmaf(hfs[r * 128 + jj], wf[jj],       s0);
            s1 = fmaf(hbs[r * 128 + jj], wf[128 + jj], s1);
        }
        out[(b0 + r) * 6 + o] = s0 + s1;
    }
}

// =====================================================================================
// DIAGNOSTIC ROUND: lstm_l0 and lstm_l1 are launched TWICE each (idempotent —
// identical inputs produce identical outputs, so the duplicate is deterministic and
// graph-safe). dur_us_new - dur_us_R7 = t_l0 + t_l1, which decomposes the total:
//   t_gemm = 4150 - 82(final) - (t_l0 + t_l1).
// =====================================================================================
extern "C" void kernel_launch(void* const* d_in, const int* in_sizes, int n_in,
                              void* d_out, int out_size)
{
    (void)in_sizes; (void)n_in; (void)out_size;
    const float* x     = (const float*)d_in[0];
    const float* Wih0f = (const float*)d_in[1];
    const float* Whh0f = (const float*)d_in[2];
    const float* b0f   = (const float*)d_in[3];
    const float* Wih0b = (const float*)d_in[4];
    const float* Whh0b = (const float*)d_in[5];
    const float* b0b   = (const float*)d_in[6];
    const float* Wih1f = (const float*)d_in[7];
    const float* Whh1f = (const float*)d_in[8];
    const float* b1f   = (const float*)d_in[9];
    const float* Wih1b = (const float*)d_in[10];
    const float* Whh1b = (const float*)d_in[11];
    const float* b1b   = (const float*)d_in[12];
    const float* Wfc   = (const float*)d_in[13];
    const float* bfc   = (const float*)d_in[14];
    float* out = (float*)d_out;

    const int SM_L0 = (2 * KSMH * 512 + 2048 + 4096 + 24) * 4;
    const int SM_G  = (256 * APITCH + 256 * WPITCH) * 4;
    const int SM_L1 = (2 * KSMH * 512 + 1024 + 2048) * 4;

    cudaFuncSetAttribute(lstm_l0,   cudaFuncAttributeMaxDynamicSharedMemorySize, SM_L0);
    cudaFuncSetAttribute(gemm_l1in, cudaFuncAttributeMaxDynamicSharedMemorySize, SM_G);
    cudaFuncSetAttribute(lstm_l1,   cudaFuncAttributeMaxDynamicSharedMemorySize, SM_L1);

    // duplicated launches (diagnostic timing decomposition)
    lstm_l0<<<dim3(64, 2), 512, SM_L0>>>(x, Wih0f, Whh0f, b0f, Wih0b, Whh0b, b0b);
    lstm_l0<<<dim3(64, 2), 512, SM_L0>>>(x, Wih0f, Whh0f, b0f, Wih0b, Whh0b, b0b);
    gemm_l1in<<<148, 512, SM_G>>>(Wih1f, b1f);
    lstm_l1<<<128, 512, SM_L1>>>(Whh1f);
    lstm_l1<<<128, 512, SM_L1>>>(Whh1f);
    final_k<<<64, 512>>>(Wih1b, b1b, Wfc, bfc, out);
}

// round 10
// speedup vs baseline: 2.0701x; 2.0656x over previous
#include <cuda_runtime.h>
#include <cuda_bf16.h>
#include <cstdint>
#include <cstddef>

#define TT_   512
#define BB_   256
#define HID   128
#define GATE  512
#define KSMH  36
#define KRGH  28

__device__ float g_h1 [(size_t)TT_ * BB_ * 2 * HID];
__device__ float g_g1f[(size_t)TT_ * BB_ * GATE];
__device__ float g_h2f[BB_ * HID];

__device__ __forceinline__ unsigned long long pack2(float lo, float hi) {
    unsigned long long r; asm("mov.b64 %0, {%1, %2};" : "=l"(r) : "f"(lo), "f"(hi)); return r;
}
__device__ __forceinline__ void ffma2(unsigned long long& d, unsigned long long a, unsigned long long b) {
    asm("fma.rn.f32x2 %0, %1, %2, %0;" : "+l"(d) : "l"(a), "l"(b));
}
__device__ __forceinline__ float sigm_f(float x) { return __fdividef(1.0f, 1.0f + __expf(-x)); }
__device__ __forceinline__ float tanh_f(float x) {
    float a = fabsf(x), e = __expf(-2.0f * a);
    return copysignf(__fdividef(1.0f - e, 1.0f + e), x);
}
// split (f0,f1) -> bf16x2 hi (f0 low half) + bf16x2 residual
__device__ __forceinline__ void bsplit(float f0, float f1, uint32_t& h2, uint32_t& l2) {
    asm("cvt.rn.bf16x2.f32 %0, %1, %2;" : "=r"(h2) : "f"(f1), "f"(f0));
    float r0 = f0 - __uint_as_float(h2 << 16);
    float r1 = f1 - __uint_as_float(h2 & 0xffff0000u);
    asm("cvt.rn.bf16x2.f32 %0, %1, %2;" : "=r"(l2) : "f"(r1), "f"(r0));
}
__device__ __forceinline__ void mma16816(float* d, uint32_t a0, uint32_t a1, uint32_t a2, uint32_t a3,
                                         uint32_t b0, uint32_t b1) {
    asm volatile("mma.sync.aligned.m16n8k16.row.col.f32.bf16.bf16.f32 "
                 "{%0,%1,%2,%3}, {%4,%5,%6,%7}, {%8,%9}, {%0,%1,%2,%3};"
                 : "+f"(d[0]), "+f"(d[1]), "+f"(d[2]), "+f"(d[3])
                 : "r"(a0), "r"(a1), "r"(a2), "r"(a3), "r"(b0), "r"(b1));
}

// ============ Kernel 1: layer-0 recurrence (R7 cfg + full-x preload) ============
extern "C" __global__ void __launch_bounds__(512, 1)
lstm_l0(const float* __restrict__ x,
        const float* __restrict__ Wih_f, const float* __restrict__ Whh_f, const float* __restrict__ bv_f,
        const float* __restrict__ Wih_b, const float* __restrict__ Whh_b, const float* __restrict__ bv_b)
{
    extern __shared__ float sm0[];
    float* Wsm = sm0;                      // [2][KSMH][512]
    float* hsm = sm0 + 2 * KSMH * 512;     // [2][128][8]
    float* gsm = hsm + 2048;               // [2][4][512]
    float* xsm = gsm + 4096;               // [512][4][3]

    const int tid = threadIdx.x, g = tid >> 8, t = tid & 255, j0 = 2 * t;
    const int dir = blockIdx.y, b0 = blockIdx.x * 4;
    const float* __restrict__ Wih = dir ? Wih_b : Wih_f;
    const float* __restrict__ Whh = dir ? Whh_b : Whh_f;
    const float* __restrict__ bv  = dir ? bv_b  : bv_f;

    for (int idx = tid; idx < 2 * KSMH * 512; idx += 512) {
        int gg = idx / (KSMH * 512), rem = idx - gg * (KSMH * 512);
        Wsm[idx] = Whh[(rem & 511) * HID + gg * 64 + (rem >> 9)];
    }
    unsigned long long wreg[KRGH];
#pragma unroll
    for (int r = 0; r < KRGH; r++) {
        int k = g * 64 + KSMH + r;
        wreg[r] = pack2(Whh[j0 * HID + k], Whh[(j0 + 1) * HID + k]);
    }
    float wA0 = Wih[j0 * 3], wA1 = Wih[j0 * 3 + 1], wA2 = Wih[j0 * 3 + 2];
    float wB0 = Wih[(j0 + 1) * 3], wB1 = Wih[(j0 + 1) * 3 + 1], wB2 = Wih[(j0 + 1) * 3 + 2];
    float bA = bv[j0], bB = bv[j0 + 1];

#pragma unroll
    for (int i = 0; i < 4; i++) hsm[tid + 512 * i] = 0.0f;
    for (int idx = tid; idx < 6144; idx += 512) {           // whole x slice
        int r = idx / 1536, rem = idx - r * 1536;
        xsm[(rem / 3) * 12 + r * 3 + (rem % 3)] = x[(size_t)(b0 + r) * 1536 + rem];
    }
    const int u = tid & 127, bb = tid >> 7;
    float c = 0.0f;
    const float* wp = Wsm + g * (KSMH * 512) + j0;
    __syncthreads();

    for (int s = 0; s < TT_; s++) {
        const int tcur = dir ? (TT_ - 1 - s) : s;
        const int pb = s & 1;
        unsigned long long acc[4];
        if (g == 0) {
            const float* xp = xsm + tcur * 12;
#pragma unroll
            for (int b = 0; b < 4; b++) {
                float x0 = xp[b * 3], x1 = xp[b * 3 + 1], x2 = xp[b * 3 + 2];
                acc[b] = pack2(fmaf(wA2, x2, fmaf(wA1, x1, fmaf(wA0, x0, bA))),
                               fmaf(wB2, x2, fmaf(wB1, x1, fmaf(wB0, x0, bB))));
            }
        } else {
#pragma unroll
            for (int b = 0; b < 4; b++) acc[b] = 0ULL;
        }
        const float* hb = hsm + pb * 1024 + g * 512;
#pragma unroll 9
        for (int kk = 0; kk < KSMH; kk++) {
            unsigned long long w2 = *reinterpret_cast<const unsigned long long*>(wp + kk * 512);
            ulonglong2 H01 = *reinterpret_cast<const ulonglong2*>(hb + kk * 8);
            ulonglong2 H23 = *reinterpret_cast<const ulonglong2*>(hb + kk * 8 + 4);
            ffma2(acc[0], w2, H01.x); ffma2(acc[1], w2, H01.y);
            ffma2(acc[2], w2, H23.x); ffma2(acc[3], w2, H23.y);
        }
#pragma unroll
        for (int r = 0; r < KRGH; r++) {
            ulonglong2 H01 = *reinterpret_cast<const ulonglong2*>(hb + (KSMH + r) * 8);
            ulonglong2 H23 = *reinterpret_cast<const ulonglong2*>(hb + (KSMH + r) * 8 + 4);
            ffma2(acc[0], wreg[r], H01.x); ffma2(acc[1], wreg[r], H01.y);
            ffma2(acc[2], wreg[r], H23.x); ffma2(acc[3], wreg[r], H23.y);
        }
#pragma unroll
        for (int b = 0; b < 4; b++)
            *reinterpret_cast<unsigned long long*>(gsm + g * 2048 + b * 512 + j0) = acc[b];
        __syncthreads();
        {
            const float* g0 = gsm + bb * 512;
            const float* g1 = gsm + 2048 + bb * 512;
            float gi = g0[u] + g1[u], gf = g0[u + 128] + g1[u + 128];
            float gg = g0[u + 256] + g1[u + 256], go = g0[u + 384] + g1[u + 384];
            c = sigm_f(gf) * c + sigm_f(gi) * tanh_f(gg);
            float h = sigm_f(go) * tanh_f(c);
            *reinterpret_cast<float2*>(hsm + (pb ^ 1) * 1024 + u * 8 + bb * 2) = make_float2(h, h);
            g_h1[((size_t)tcur * BB_ + b0 + bb) * (2 * HID) + dir * HID + u] = h;
        }
        __syncthreads();
    }
}

// ============ Kernel 2: GEMM via bf16 tensor cores, hi/lo split (3-pass) ============
#define WPB 264   // bf16 row pitch (conflict-free)
extern "C" __global__ void __launch_bounds__(256, 1)
gemm_l1in(const float* __restrict__ W, const float* __restrict__ bias)
{
    extern __shared__ __nv_bfloat16 smb[];
    __nv_bfloat16* Whi = smb;                      // [128][WPB]
    __nv_bfloat16* Wlo = Whi + 128 * WPB;
    __nv_bfloat16* Ahi = Wlo + 128 * WPB;          // [64][WPB]
    __nv_bfloat16* Alo = Ahi + 64 * WPB;
    float* biasS = reinterpret_cast<float*>(Alo + 64 * WPB);   // [128]

    const int tid = threadIdx.x;
    const int jblk = blockIdx.x & 3, tg = blockIdx.x >> 2;

    for (int idx = tid; idx < 128 * 128; idx += 256) {          // W chunk -> bf16 hi/lo
        int jj = idx >> 7, kp = idx & 127;
        float2 w = *reinterpret_cast<const float2*>(W + ((size_t)(jblk * 128 + jj)) * 256 + 2 * kp);
        uint32_t h2, l2; bsplit(w.x, w.y, h2, l2);
        *reinterpret_cast<uint32_t*>(Whi + jj * WPB + 2 * kp) = h2;
        *reinterpret_cast<uint32_t*>(Wlo + jj * WPB + 2 * kp) = l2;
    }
    if (tid < 128) biasS[tid] = bias[jblk * 128 + tid];

    const int wid = tid >> 5, lane = tid & 31;
    const int wm = wid >> 1, wn = wid & 1;          // 4 x 2 warps
    const int m0 = wm * 16, n0 = wn * 64;
    const int gid = lane >> 2, tig = lane & 3;
    __syncthreads();

    for (int tile = tg; tile < 2048; tile += 37) {
        const size_t r0 = (size_t)tile * 64;
        for (int idx = tid; idx < 64 * 128; idx += 256) {       // A tile -> bf16 hi/lo
            int row = idx >> 7, kp = idx & 127;
            float2 a = *reinterpret_cast<const float2*>(g_h1 + (r0 + row) * 256 + 2 * kp);
            uint32_t h2, l2; bsplit(a.x, a.y, h2, l2);
            *reinterpret_cast<uint32_t*>(Ahi + row * WPB + 2 * kp) = h2;
            *reinterpret_cast<uint32_t*>(Alo + row * WPB + 2 * kp) = l2;
        }
        __syncthreads();

        float acc[8][4];
#pragma unroll
        for (int nf = 0; nf < 8; nf++) {
            float bv0 = biasS[n0 + nf * 8 + tig * 2], bv1 = biasS[n0 + nf * 8 + tig * 2 + 1];
            acc[nf][0] = bv0; acc[nf][1] = bv1; acc[nf][2] = bv0; acc[nf][3] = bv1;
        }
#pragma unroll 4
        for (int ks = 0; ks < 16; ks++) {
            const int k0 = ks * 16;
            const __nv_bfloat16* arow = Ahi + (m0 + gid) * WPB + k0 + tig * 2;
            const __nv_bfloat16* arowl = Alo + (m0 + gid) * WPB + k0 + tig * 2;
            uint32_t ah0 = *reinterpret_cast<const uint32_t*>(arow);
            uint32_t ah1 = *reinterpret_cast<const uint32_t*>(arow + 8 * WPB);
            uint32_t ah2 = *reinterpret_cast<const uint32_t*>(arow + 8);
            uint32_t ah3 = *reinterpret_cast<const uint32_t*>(arow + 8 * WPB + 8);
            uint32_t al0 = *reinterpret_cast<const uint32_t*>(arowl);
            uint32_t al1 = *reinterpret_cast<const uint32_t*>(arowl + 8 * WPB);
            uint32_t al2 = *reinterpret_cast<const uint32_t*>(arowl + 8);
            uint32_t al3 = *reinterpret_cast<const uint32_t*>(arowl + 8 * WPB + 8);
#pragma unroll
            for (int nf = 0; nf < 8; nf++) {
                const __nv_bfloat16* brow = Whi + (n0 + nf * 8 + gid) * WPB + k0 + tig * 2;
                const __nv_bfloat16* browl = Wlo + (n0 + nf * 8 + gid) * WPB + k0 + tig * 2;
                uint32_t bh0 = *reinterpret_cast<const uint32_t*>(brow);
                uint32_t bh1 = *reinterpret_cast<const uint32_t*>(brow + 8);
                uint32_t bl0 = *reinterpret_cast<const uint32_t*>(browl);
                uint32_t bl1 = *reinterpret_cast<const uint32_t*>(browl + 8);
                mma16816(acc[nf], ah0, ah1, ah2, ah3, bh0, bh1);
                mma16816(acc[nf], al0, al1, al2, al3, bh0, bh1);
                mma16816(acc[nf], ah0, ah1, ah2, ah3, bl0, bl1);
            }
        }
        const size_t row = r0 + m0 + gid;
        const int col = jblk * 128 + n0 + tig * 2;
#pragma unroll
        for (int nf = 0; nf < 8; nf++) {
            *reinterpret_cast<float2*>(g_g1f + row * GATE + col + nf * 8) =
                make_float2(acc[nf][0], acc[nf][1]);
            *reinterpret_cast<float2*>(g_g1f + (row + 8) * GATE + col + nf * 8) =
                make_float2(acc[nf][2], acc[nf][3]);
        }
        __syncthreads();
    }
}

// ============ Kernel 3: layer-1 recurrence (R7 cfg, unchanged) ============
extern "C" __global__ void __launch_bounds__(512, 1)
lstm_l1(const float* __restrict__ Whh)
{
    extern __shared__ float sm1[];
    float* Wsm = sm1;
    float* hsm = sm1 + 2 * KSMH * 512;
    float* gsm = hsm + 1024;

    const int tid = threadIdx.x, g = tid >> 8, t = tid & 255, j0 = 2 * t;
    const int b0 = blockIdx.x * 2;

    for (int idx = tid; idx < 2 * KSMH * 512; idx += 512) {
        int gg = idx / (KSMH * 512), rem = idx - gg * (KSMH * 512);
        Wsm[idx] = Whh[(rem & 511) * HID + gg * 64 + (rem >> 9)];
    }
    unsigned long long wreg[KRGH];
#pragma unroll
    for (int r = 0; r < KRGH; r++) {
        int k = g * 64 + KSMH + r;
        wreg[r] = pack2(Whh[j0 * HID + k], Whh[(j0 + 1) * HID + k]);
    }
#pragma unroll
    for (int i = 0; i < 2; i++) hsm[tid + 512 * i] = 0.0f;

    unsigned long long p0 = 0ULL, p1 = 0ULL;
    if (g == 0) {
        p0 = *reinterpret_cast<const unsigned long long*>(g_g1f + (size_t)(b0 + 0) * GATE + j0);
        p1 = *reinterpret_cast<const unsigned long long*>(g_g1f + (size_t)(b0 + 1) * GATE + j0);
    }
    const int u = tid & 127, bsel = (tid >> 7) & 1;
    const bool docell = tid < 256;
    float c = 0.0f;
    const float* wp = Wsm + g * (KSMH * 512) + j0;
    __syncthreads();

    for (int s = 0; s < TT_; s++) {
        const int pb = s & 1;
        unsigned long long acc0 = p0, acc1 = p1;
        if (g == 0 && s + 1 < TT_) {
            size_t rn = (size_t)(s + 1) * BB_ + b0;
            p0 = *reinterpret_cast<const unsigned long long*>(g_g1f + rn * GATE + j0);
            p1 = *reinterpret_cast<const unsigned long long*>(g_g1f + (rn + 1) * GATE + j0);
        }
        const float* hb = hsm + pb * 512 + g * 256;
#pragma unroll 9
        for (int kk = 0; kk < KSMH; kk++) {
            unsigned long long w2 = *reinterpret_cast<const unsigned long long*>(wp + kk * 512);
            ulonglong2 H = *reinterpret_cast<const ulonglong2*>(hb + kk * 4);
            ffma2(acc0, w2, H.x); ffma2(acc1, w2, H.y);
        }
#pragma unroll
        for (int r = 0; r < KRGH; r++) {
            ulonglong2 H = *reinterpret_cast<const ulonglong2*>(hb + (KSMH + r) * 4);
            ffma2(acc0, wreg[r], H.x); ffma2(acc1, wreg[r], H.y);
        }
        *reinterpret_cast<unsigned long long*>(gsm + g * 1024 + j0) = acc0;
        *reinterpret_cast<unsigned long long*>(gsm + g * 1024 + 512 + j0) = acc1;
        __syncthreads();
        if (docell) {
            const float* ga = gsm + bsel * 512;
            const float* gb2 = gsm + 1024 + bsel * 512;
            float gi = ga[u] + gb2[u], gf = ga[u + 128] + gb2[u + 128];
            float gg = ga[u + 256] + gb2[u + 256], go = ga[u + 384] + gb2[u + 384];
            c = sigm_f(gf) * c + sigm_f(gi) * tanh_f(gg);
            float h = sigm_f(go) * tanh_f(c);
            *reinterpret_cast<float2*>(hsm + (pb ^ 1) * 512 + u * 4 + bsel * 2) = make_float2(h, h);
            if (s == TT_ - 1) g_h2f[(b0 + bsel) * HID + u] = h;
        }
        __syncthreads();
    }
}

// ============ Kernel 4: layer-1 backward one step + FC (unchanged) ============
extern "C" __global__ void __launch_bounds__(512, 1)
final_k(const float* __restrict__ Wihb, const float* __restrict__ bvb,
        const float* __restrict__ Wfc,  const float* __restrict__ bfc,
        float* __restrict__ out)
{
    __shared__ float h1s[1024], hfs[512], gates[2048], hbs[512];
    const int tid = threadIdx.x, b0 = blockIdx.x * 4;

    for (int idx = tid; idx < 1024; idx += 512) {
        int r = idx >> 8, k = idx & 255;
        h1s[idx] = g_h1[((size_t)(TT_ - 1) * BB_ + b0 + r) * 256 + k];
    }
    if (tid < 512) hfs[tid] = g_h2f[b0 * HID + tid];
    __syncthreads();

    float acc[4];
    const float bj = bvb[tid];
#pragma unroll
    for (int r = 0; r < 4; r++) acc[r] = bj;
    const float* wr = Wihb + (size_t)tid * 256;
#pragma unroll 4
    for (int k = 0; k < 256; k++) {
        float w = wr[k];
#pragma unroll
        for (int r = 0; r < 4; r++) acc[r] = fmaf(h1s[r * 256 + k], w, acc[r]);
    }
#pragma unroll
    for (int r = 0; r < 4; r++) gates[r * 512 + tid] = acc[r];
    __syncthreads();
    {
        int r = tid >> 7, u = tid & 127;
        float c = sigm_f(gates[r * 512 + u]) * tanh_f(gates[r * 512 + u + 256]);
        hbs[r * 128 + u] = sigm_f(gates[r * 512 + u + 384]) * tanh_f(c);
    }
    __syncthreads();
    if (tid < 24) {
        int r = tid / 6, o = tid % 6;
        const float* wf = Wfc + o * 256;
        float s0 = bfc[o], s1 = 0.0f;
#pragma unroll 4
        for (int jj = 0; jj < 128; jj++) {
            s0 = fmaf(hfs[r * 128 + jj], wf[jj], s0);
            s1 = fmaf(hbs[r * 128 + jj], wf[128 + jj], s1);
        }
        out[(b0 + r) * 6 + o] = s0 + s1;
    }
}

extern "C" void kernel_launch(void* const* d_in, const int* in_sizes, int n_in,
                              void* d_out, int out_size)
{
    (void)in_sizes; (void)n_in; (void)out_size;
    const float* x     = (const float*)d_in[0];
    const float* Wih0f = (const float*)d_in[1];
    const float* Whh0f = (const float*)d_in[2];
    const float* b0f   = (const float*)d_in[3];
    const float* Wih0b = (const float*)d_in[4];
    const float* Whh0b = (const float*)d_in[5];
    const float* b0b   = (const float*)d_in[6];
    const float* Wih1f = (const float*)d_in[7];
    const float* Whh1f = (const float*)d_in[8];
    const float* b1f   = (const float*)d_in[9];
    const float* Wih1b = (const float*)d_in[10];
    const float* Whh1b = (const float*)d_in[11];
    const float* b1b   = (const float*)d_in[12];
    const float* Wfc   = (const float*)d_in[13];
    const float* bfc   = (const float*)d_in[14];
    float* out = (float*)d_out;

    const int SM_L0 = (2 * KSMH * 512 + 2048 + 4096) * 4 + 6144 * 4;   // 196,608 B
    const int SM_G  = (2 * 128 * WPB + 2 * 64 * WPB) * 2 + 512;        // 203,264 B
    const int SM_L1 = (2 * KSMH * 512 + 1024 + 2048) * 4;              // 159,744 B

    cudaFuncSetAttribute(lstm_l0,   cudaFuncAttributeMaxDynamicSharedMemorySize, SM_L0);
    cudaFuncSetAttribute(gemm_l1in, cudaFuncAttributeMaxDynamicSharedMemorySize, SM_G);
    cudaFuncSetAttribute(lstm_l1,   cudaFuncAttributeMaxDynamicSharedMemorySize, SM_L1);

    lstm_l0<<<dim3(64, 2), 512, SM_L0>>>(x, Wih0f, Whh0f, b0f, Wih0b, Whh0b, b0b);
    gemm_l1in<<<148, 256, SM_G>>>(Wih1f, b1f);
    lstm_l1<<<128, 512, SM_L1>>>(Whh1f);
    final_k<<<64, 512>>>(Wih1b, b1b, Wfc, bfc, out);
}

// round 11
// speedup vs baseline: 2.3661x; 1.1430x over previous
#include <cuda_runtime.h>
#include <cuda_bf16.h>
#include <cstdint>
#include <cstddef>

#define TT_   512
#define BB_   256
#define HID   128
#define GATE  512
#define KSMH  36
#define KRGH  28

__device__ float g_h1 [(size_t)TT_ * BB_ * 2 * HID];
__device__ float g_g1f[(size_t)TT_ * BB_ * GATE];
__device__ float g_h2f[BB_ * HID];

__device__ __forceinline__ unsigned long long pack2(float lo, float hi) {
    unsigned long long r; asm("mov.b64 %0, {%1, %2};" : "=l"(r) : "f"(lo), "f"(hi)); return r;
}
__device__ __forceinline__ void ffma2(unsigned long long& d, unsigned long long a, unsigned long long b) {
    asm("fma.rn.f32x2 %0, %1, %2, %0;" : "+l"(d) : "l"(a), "l"(b));
}
__device__ __forceinline__ float sigm_f(float x) { return __fdividef(1.0f, 1.0f + __expf(-x)); }
__device__ __forceinline__ float tanh_f(float x) {
    float a = fabsf(x), e = __expf(-2.0f * a);
    return copysignf(__fdividef(1.0f - e, 1.0f + e), x);
}
__device__ __forceinline__ void bsplit(float f0, float f1, uint32_t& h2, uint32_t& l2) {
    asm("cvt.rn.bf16x2.f32 %0, %1, %2;" : "=r"(h2) : "f"(f1), "f"(f0));
    float r0 = f0 - __uint_as_float(h2 << 16);
    float r1 = f1 - __uint_as_float(h2 & 0xffff0000u);
    asm("cvt.rn.bf16x2.f32 %0, %1, %2;" : "=r"(l2) : "f"(r1), "f"(r0));
}
__device__ __forceinline__ void mma16816(float* d, uint32_t a0, uint32_t a1, uint32_t a2, uint32_t a3,
                                         uint32_t b0, uint32_t b1) {
    asm volatile("mma.sync.aligned.m16n8k16.row.col.f32.bf16.bf16.f32 "
                 "{%0,%1,%2,%3}, {%4,%5,%6,%7}, {%8,%9}, {%0,%1,%2,%3};"
                 : "+f"(d[0]), "+f"(d[1]), "+f"(d[2]), "+f"(d[3])
                 : "r"(a0), "r"(a1), "r"(a2), "r"(a3), "r"(b0), "r"(b1));
}

// ============ Kernel 1: layer-0 recurrence via TENSOR CORES ============
// grid (64,2), 512 thr (16 warps). 4 real batch rows padded to M=16.
// Per step: gates[16,512] = A[16,128] @ Whh^T via 3-pass hi/lo bf16 MMA.
// Whi in smem (pitch 68 u32, conflict-free); Wlo in 64 regs/thread; x-proj in cell phase.
// smem byte offsets:
#define L0_XS 0                      // x slice   [512][12] f32   24576
#define L0_GS 24576                  // gates     [4][514] f32     8224
#define L0_WI 32800                  // Wih+b     [512][4] f32     8192
#define L0_WH 40992                  // Whi bf16  [512][136]     139264
#define L0_AH 180256                 // Ahi bf16  [16][136]        4352
#define L0_AL 184608                 // Alo bf16  [16][136]        4352
#define L0_SM 188960

extern "C" __global__ void __launch_bounds__(512, 1)
lstm_l0(const float* __restrict__ x,
        const float* __restrict__ Wih_f, const float* __restrict__ Whh_f, const float* __restrict__ bv_f,
        const float* __restrict__ Wih_b, const float* __restrict__ Whh_b, const float* __restrict__ bv_b)
{
    extern __shared__ char smraw[];
    float*    xsm  = reinterpret_cast<float*>(smraw + L0_XS);
    float*    gsm  = reinterpret_cast<float*>(smraw + L0_GS);
    float*    wihs = reinterpret_cast<float*>(smraw + L0_WI);
    uint32_t* Whi  = reinterpret_cast<uint32_t*>(smraw + L0_WH);   // u32 = 2 bf16, pitch 68
    __nv_bfloat16* Ahi = reinterpret_cast<__nv_bfloat16*>(smraw + L0_AH);  // pitch 136
    __nv_bfloat16* Alo = reinterpret_cast<__nv_bfloat16*>(smraw + L0_AL);

    const int tid = threadIdx.x;
    const int dir = blockIdx.y, b0 = blockIdx.x * 4;
    const float* __restrict__ Wih = dir ? Wih_b : Wih_f;
    const float* __restrict__ Whh = dir ? Whh_b : Whh_f;
    const float* __restrict__ bv  = dir ? bv_b  : bv_f;

    const int wid = tid >> 5, lane = tid & 31;
    const int gid = lane >> 2, tig = lane & 3;
    const int n0 = wid * 32;

    // Whi (cooperative): Whi[j][kp] u32
    for (int idx = tid; idx < 512 * 64; idx += 512) {
        int j = idx >> 6, kp = idx & 63;
        float2 w = *reinterpret_cast<const float2*>(Whh + j * 128 + kp * 2);
        uint32_t h2, l2; bsplit(w.x, w.y, h2, l2);
        Whi[j * 68 + kp] = h2;
    }
    // Wlo fragments (per-thread registers)
    uint32_t wlo[4][8][2];
#pragma unroll
    for (int nf = 0; nf < 4; nf++) {
        const int j = n0 + nf * 8 + gid;
        const float* wr = Whh + j * 128;
#pragma unroll
        for (int ks = 0; ks < 8; ks++) {
            int k = ks * 16 + tig * 2;
            float2 wa = *reinterpret_cast<const float2*>(wr + k);
            float2 wb = *reinterpret_cast<const float2*>(wr + k + 8);
            uint32_t h2, l2;
            bsplit(wa.x, wa.y, h2, l2); wlo[nf][ks][0] = l2;
            bsplit(wb.x, wb.y, h2, l2); wlo[nf][ks][1] = l2;
        }
    }
    // Wih + bias -> smem float4 per gate column
    if (tid < 512) {
        wihs[tid * 4 + 0] = Wih[tid * 3 + 0];
        wihs[tid * 4 + 1] = Wih[tid * 3 + 1];
        wihs[tid * 4 + 2] = Wih[tid * 3 + 2];
        wihs[tid * 4 + 3] = bv[tid];
    }
    // whole x slice: xsm[t][r][i]
    for (int idx = tid; idx < 6144; idx += 512) {
        int r = idx / 1536, rem = idx - r * 1536;
        xsm[(rem / 3) * 12 + r * 3 + (rem % 3)] = x[(size_t)(b0 + r) * 1536 + rem];
    }
    // zero A buffers (rows 4..15 stay zero forever)
    for (int idx = tid; idx < 16 * 68; idx += 512) {
        reinterpret_cast<uint32_t*>(Ahi)[idx] = 0u;
        reinterpret_cast<uint32_t*>(Alo)[idx] = 0u;
    }
    const int u = tid & 127, b = tid >> 7;
    float c = 0.0f;
    __syncthreads();

    for (int s = 0; s < TT_; s++) {
        const int tcur = dir ? (TT_ - 1 - s) : s;

        // ---- MMA phase: gates = Ahi*Whi + Alo*Whi + Ahi*Wlo ----
        float acc[4][4];
#pragma unroll
        for (int nf = 0; nf < 4; nf++) { acc[nf][0] = acc[nf][1] = acc[nf][2] = acc[nf][3] = 0.0f; }
        const uint32_t* Ahi32 = reinterpret_cast<const uint32_t*>(Ahi);
        const uint32_t* Alo32 = reinterpret_cast<const uint32_t*>(Alo);
#pragma unroll
        for (int ks = 0; ks < 8; ks++) {
            const int abase = gid * 68 + ks * 8 + tig;
            uint32_t ah0 = Ahi32[abase];
            uint32_t ah1 = Ahi32[abase + 8 * 68];
            uint32_t ah2 = Ahi32[abase + 4];
            uint32_t ah3 = Ahi32[abase + 8 * 68 + 4];
            uint32_t al0 = Alo32[abase];
            uint32_t al1 = Alo32[abase + 8 * 68];
            uint32_t al2 = Alo32[abase + 4];
            uint32_t al3 = Alo32[abase + 8 * 68 + 4];
#pragma unroll
            for (int nf = 0; nf < 4; nf++) {
                const int bbase = (n0 + nf * 8 + gid) * 68 + ks * 8 + tig;
                uint32_t bh0 = Whi[bbase];
                uint32_t bh1 = Whi[bbase + 4];
                mma16816(acc[nf], ah0, ah1, ah2, ah3, bh0, bh1);
                mma16816(acc[nf], al0, al1, al2, al3, bh0, bh1);
                mma16816(acc[nf], ah0, ah1, ah2, ah3, wlo[nf][ks][0], wlo[nf][ks][1]);
            }
        }
        // store real rows' gates (rows = gid < 4)
        if (gid < 4) {
#pragma unroll
            for (int nf = 0; nf < 4; nf++)
                *reinterpret_cast<float2*>(gsm + gid * 514 + n0 + nf * 8 + tig * 2) =
                    make_float2(acc[nf][0], acc[nf][1]);
        }
        __syncthreads();

        // ---- cell phase: 1 cell (u, b) per thread ----
        {
            const float* xp = xsm + tcur * 12 + b * 3;
            float x0 = xp[0], x1 = xp[1], x2 = xp[2];
            float pre[4];
#pragma unroll
            for (int g = 0; g < 4; g++) {
                int j = g * 128 + u;
                float4 wv = *reinterpret_cast<const float4*>(wihs + j * 4);
                pre[g] = gsm[b * 514 + j] + fmaf(wv.x, x0, fmaf(wv.y, x1, fmaf(wv.z, x2, wv.w)));
            }
            c = sigm_f(pre[1]) * c + sigm_f(pre[0]) * tanh_f(pre[2]);
            float h = sigm_f(pre[3]) * tanh_f(c);

            __nv_bfloat16 hh = __float2bfloat16(h);
            Ahi[b * 136 + u] = hh;
            Alo[b * 136 + u] = __float2bfloat16(h - __bfloat162float(hh));
            g_h1[((size_t)tcur * BB_ + b0 + b) * (2 * HID) + dir * HID + u] = h;
        }
        __syncthreads();
    }
}

// ============ Kernel 2: GEMM via bf16 tensor cores (R10, measured-pass) ============
#define WPB 264
extern "C" __global__ void __launch_bounds__(256, 1)
gemm_l1in(const float* __restrict__ W, const float* __restrict__ bias)
{
    extern __shared__ __nv_bfloat16 smb[];
    __nv_bfloat16* Whi = smb;
    __nv_bfloat16* Wlo = Whi + 128 * WPB;
    __nv_bfloat16* Ahi = Wlo + 128 * WPB;
    __nv_bfloat16* Alo = Ahi + 64 * WPB;
    float* biasS = reinterpret_cast<float*>(Alo + 64 * WPB);

    const int tid = threadIdx.x;
    const int jblk = blockIdx.x & 3, tg = blockIdx.x >> 2;

    for (int idx = tid; idx < 128 * 128; idx += 256) {
        int jj = idx >> 7, kp = idx & 127;
        float2 w = *reinterpret_cast<const float2*>(W + ((size_t)(jblk * 128 + jj)) * 256 + 2 * kp);
        uint32_t h2, l2; bsplit(w.x, w.y, h2, l2);
        *reinterpret_cast<uint32_t*>(Whi + jj * WPB + 2 * kp) = h2;
        *reinterpret_cast<uint32_t*>(Wlo + jj * WPB + 2 * kp) = l2;
    }
    if (tid < 128) biasS[tid] = bias[jblk * 128 + tid];

    const int wid = tid >> 5, lane = tid & 31;
    const int wm = wid >> 1, wn = wid & 1;
    const int m0 = wm * 16, n0 = wn * 64;
    const int gid = lane >> 2, tig = lane & 3;
    __syncthreads();

    for (int tile = tg; tile < 2048; tile += 37) {
        const size_t r0 = (size_t)tile * 64;
        for (int idx = tid; idx < 64 * 128; idx += 256) {
            int row = idx >> 7, kp = idx & 127;
            float2 a = *reinterpret_cast<const float2*>(g_h1 + (r0 + row) * 256 + 2 * kp);
            uint32_t h2, l2; bsplit(a.x, a.y, h2, l2);
            *reinterpret_cast<uint32_t*>(Ahi + row * WPB + 2 * kp) = h2;
            *reinterpret_cast<uint32_t*>(Alo + row * WPB + 2 * kp) = l2;
        }
        __syncthreads();

        float acc[8][4];
#pragma unroll
        for (int nf = 0; nf < 8; nf++) {
            float bv0 = biasS[n0 + nf * 8 + tig * 2], bv1 = biasS[n0 + nf * 8 + tig * 2 + 1];
            acc[nf][0] = bv0; acc[nf][1] = bv1; acc[nf][2] = bv0; acc[nf][3] = bv1;
        }
#pragma unroll 4
        for (int ks = 0; ks < 16; ks++) {
            const int k0 = ks * 16;
            const __nv_bfloat16* arow = Ahi + (m0 + gid) * WPB + k0 + tig * 2;
            const __nv_bfloat16* arowl = Alo + (m0 + gid) * WPB + k0 + tig * 2;
            uint32_t ah0 = *reinterpret_cast<const uint32_t*>(arow);
            uint32_t ah1 = *reinterpret_cast<const uint32_t*>(arow + 8 * WPB);
            uint32_t ah2 = *reinterpret_cast<const uint32_t*>(arow + 8);
            uint32_t ah3 = *reinterpret_cast<const uint32_t*>(arow + 8 * WPB + 8);
            uint32_t al0 = *reinterpret_cast<const uint32_t*>(arowl);
            uint32_t al1 = *reinterpret_cast<const uint32_t*>(arowl + 8 * WPB);
            uint32_t al2 = *reinterpret_cast<const uint32_t*>(arowl + 8);
            uint32_t al3 = *reinterpret_cast<const uint32_t*>(arowl + 8 * WPB + 8);
#pragma unroll
            for (int nf = 0; nf < 8; nf++) {
                const __nv_bfloat16* brow = Whi + (n0 + nf * 8 + gid) * WPB + k0 + tig * 2;
                const __nv_bfloat16* browl = Wlo + (n0 + nf * 8 + gid) * WPB + k0 + tig * 2;
                uint32_t bh0 = *reinterpret_cast<const uint32_t*>(brow);
                uint32_t bh1 = *reinterpret_cast<const uint32_t*>(brow + 8);
                uint32_t bl0 = *reinterpret_cast<const uint32_t*>(browl);
                uint32_t bl1 = *reinterpret_cast<const uint32_t*>(browl + 8);
                mma16816(acc[nf], ah0, ah1, ah2, ah3, bh0, bh1);
                mma16816(acc[nf], al0, al1, al2, al3, bh0, bh1);
                mma16816(acc[nf], ah0, ah1, ah2, ah3, bl0, bl1);
            }
        }
        const size_t row = r0 + m0 + gid;
        const int col = jblk * 128 + n0 + tig * 2;
#pragma unroll
        for (int nf = 0; nf < 8; nf++) {
            *reinterpret_cast<float2*>(g_g1f + row * GATE + col + nf * 8) =
                make_float2(acc[nf][0], acc[nf][1]);
            *reinterpret_cast<float2*>(g_g1f + (row + 8) * GATE + col + nf * 8) =
                make_float2(acc[nf][2], acc[nf][3]);
        }
        __syncthreads();
    }
}

// ============ Kernel 3: layer-1 recurrence (R7/R10 measured-pass) ============
extern "C" __global__ void __launch_bounds__(512, 1)
lstm_l1(const float* __restrict__ Whh)
{
    extern __shared__ float sm1[];
    float* Wsm = sm1;
    float* hsm = sm1 + 2 * KSMH * 512;
    float* gsm = hsm + 1024;

    const int tid = threadIdx.x, g = tid >> 8, t = tid & 255, j0 = 2 * t;
    const int b0 = blockIdx.x * 2;

    for (int idx = tid; idx < 2 * KSMH * 512; idx += 512) {
        int gg = idx / (KSMH * 512), rem = idx - gg * (KSMH * 512);
        Wsm[idx] = Whh[(rem & 511) * HID + gg * 64 + (rem >> 9)];
    }
    unsigned long long wreg[KRGH];
#pragma unroll
    for (int r = 0; r < KRGH; r++) {
        int k = g * 64 + KSMH + r;
        wreg[r] = pack2(Whh[j0 * HID + k], Whh[(j0 + 1) * HID + k]);
    }
#pragma unroll
    for (int i = 0; i < 2; i++) hsm[tid + 512 * i] = 0.0f;

    unsigned long long p0 = 0ULL, p1 = 0ULL;
    if (g == 0) {
        p0 = *reinterpret_cast<const unsigned long long*>(g_g1f + (size_t)(b0 + 0) * GATE + j0);
        p1 = *reinterpret_cast<const unsigned long long*>(g_g1f + (size_t)(b0 + 1) * GATE + j0);
    }
    const int u = tid & 127, bsel = (tid >> 7) & 1;
    const bool docell = tid < 256;
    float c = 0.0f;
    const float* wp = Wsm + g * (KSMH * 512) + j0;
    __syncthreads();

    for (int s = 0; s < TT_; s++) {
        const int pb = s & 1;
        unsigned long long acc0 = p0, acc1 = p1;
        if (g == 0 && s + 1 < TT_) {
            size_t rn = (size_t)(s + 1) * BB_ + b0;
            p0 = *reinterpret_cast<const unsigned long long*>(g_g1f + rn * GATE + j0);
            p1 = *reinterpret_cast<const unsigned long long*>(g_g1f + (rn + 1) * GATE + j0);
        }
        const float* hb = hsm + pb * 512 + g * 256;
#pragma unroll 9
        for (int kk = 0; kk < KSMH; kk++) {
            unsigned long long w2 = *reinterpret_cast<const unsigned long long*>(wp + kk * 512);
            ulonglong2 H = *reinterpret_cast<const ulonglong2*>(hb + kk * 4);
            ffma2(acc0, w2, H.x); ffma2(acc1, w2, H.y);
        }
#pragma unroll
        for (int r = 0; r < KRGH; r++) {
            ulonglong2 H = *reinterpret_cast<const ulonglong2*>(hb + (KSMH + r) * 4);
            ffma2(acc0, wreg[r], H.x); ffma2(acc1, wreg[r], H.y);
        }
        *reinterpret_cast<unsigned long long*>(gsm + g * 1024 + j0) = acc0;
        *reinterpret_cast<unsigned long long*>(gsm + g * 1024 + 512 + j0) = acc1;
        __syncthreads();
        if (docell) {
            const float* ga = gsm + bsel * 512;
            const float* gb2 = gsm + 1024 + bsel * 512;
            float gi = ga[u] + gb2[u], gf = ga[u + 128] + gb2[u + 128];
            float gg = ga[u + 256] + gb2[u + 256], go = ga[u + 384] + gb2[u + 384];
            c = sigm_f(gf) * c + sigm_f(gi) * tanh_f(gg);
            float h = sigm_f(go) * tanh_f(c);
            *reinterpret_cast<float2*>(hsm + (pb ^ 1) * 512 + u * 4 + bsel * 2) = make_float2(h, h);
            if (s == TT_ - 1) g_h2f[(b0 + bsel) * HID + u] = h;
        }
        __syncthreads();
    }
}

// ============ Kernel 4: layer-1 backward one step + FC (measured-pass) ============
extern "C" __global__ void __launch_bounds__(512, 1)
final_k(const float* __restrict__ Wihb, const float* __restrict__ bvb,
        const float* __restrict__ Wfc,  const float* __restrict__ bfc,
        float* __restrict__ out)
{
    __shared__ float h1s[1024], hfs[512], gates[2048], hbs[512];
    const int tid = threadIdx.x, b0 = blockIdx.x * 4;

    for (int idx = tid; idx < 1024; idx += 512) {
        int r = idx >> 8, k = idx & 255;
        h1s[idx] = g_h1[((size_t)(TT_ - 1) * BB_ + b0 + r) * 256 + k];
    }
    if (tid < 512) hfs[tid] = g_h2f[b0 * HID + tid];
    __syncthreads();

    float acc[4];
    const float bj = bvb[tid];
#pragma unroll
    for (int r = 0; r < 4; r++) acc[r] = bj;
    const float* wr = Wihb + (size_t)tid * 256;
#pragma unroll 4
    for (int k = 0; k < 256; k++) {
        float w = wr[k];
#pragma unroll
        for (int r = 0; r < 4; r++) acc[r] = fmaf(h1s[r * 256 + k], w, acc[r]);
    }
#pragma unroll
    for (int r = 0; r < 4; r++) gates[r * 512 + tid] = acc[r];
    __syncthreads();
    {
        int r = tid >> 7, u = tid & 127;
        float c = sigm_f(gates[r * 512 + u]) * tanh_f(gates[r * 512 + u + 256]);
        hbs[r * 128 + u] = sigm_f(gates[r * 512 + u + 384]) * tanh_f(c);
    }
    __syncthreads();
    if (tid < 24) {
        int r = tid / 6, o = tid % 6;
        const float* wf = Wfc + o * 256;
        float s0 = bfc[o], s1 = 0.0f;
#pragma unroll 4
        for (int jj = 0; jj < 128; jj++) {
            s0 = fmaf(hfs[r * 128 + jj], wf[jj], s0);
            s1 = fmaf(hbs[r * 128 + jj], wf[128 + jj], s1);
        }
        out[(b0 + r) * 6 + o] = s0 + s1;
    }
}

extern "C" void kernel_launch(void* const* d_in, const int* in_sizes, int n_in,
                              void* d_out, int out_size)
{
    (void)in_sizes; (void)n_in; (void)out_size;
    const float* x     = (const float*)d_in[0];
    const float* Wih0f = (const float*)d_in[1];
    const float* Whh0f = (const float*)d_in[2];
    const float* b0f   = (const float*)d_in[3];
    const float* Wih0b = (const float*)d_in[4];
    const float* Whh0b = (const float*)d_in[5];
    const float* b0b   = (const float*)d_in[6];
    const float* Wih1f = (const float*)d_in[7];
    const float* Whh1f = (const float*)d_in[8];
    const float* b1f   = (const float*)d_in[9];
    const float* Wih1b = (const float*)d_in[10];
    const float* Whh1b = (const float*)d_in[11];
    const float* b1b   = (const float*)d_in[12];
    const float* Wfc   = (const float*)d_in[13];
    const float* bfc   = (const float*)d_in[14];
    float* out = (float*)d_out;

    const int SM_L0 = L0_SM;                                       // 188,960 B
    const int SM_G  = (2 * 128 * WPB + 2 * 64 * WPB) * 2 + 512;    // 203,264 B
    const int SM_L1 = (2 * KSMH * 512 + 1024 + 2048) * 4;          // 159,744 B

    cudaFuncSetAttribute(lstm_l0,   cudaFuncAttributeMaxDynamicSharedMemorySize, SM_L0);
    cudaFuncSetAttribute(gemm_l1in, cudaFuncAttributeMaxDynamicSharedMemorySize, SM_G);
    cudaFuncSetAttribute(lstm_l1,   cudaFuncAttributeMaxDynamicSharedMemorySize, SM_L1);

    lstm_l0<<<dim3(64, 2), 512, SM_L0>>>(x, Wih0f, Whh0f, b0f, Wih0b, Whh0b, b0b);
    gemm_l1in<<<148, 256, SM_G>>>(Wih1f, b1f);
    lstm_l1<<<128, 512, SM_L1>>>(Whh1f);
    final_k<<<64, 512>>>(Wih1b, b1b, Wfc, bfc, out);
}